// round 3
// baseline (speedup 1.0000x reference)
#include <cuda_runtime.h>
#include <cuda_bf16.h>

// ---------------------------------------------------------------------------
// WindowAttention (Swin-style, with the reference's "faithful raw view"
// channel/token scramble). All fp32.
//
// Shapes: B=16, C=768, H=W=56, window 7x7 (N=49), heads=24, hd=32,
// B_ = 16*64 = 1024 windows, T = 50176 tokens.
//
// Key layout identity derived from the reference:
//   xt[n][c] = window_hwc.flat[c*49 + n]     (per window)
// i.e. the GEMM A-matrix per window is the (49 x 768) hwc matrix stored
// COLUMN-major. So with an hwc-ordered scratch buffer and M-tile = 49
// (one window), A-tiles are contiguous 49*BK-float chunks.
// Also: the final reshape (B_,N,C)->(B,C,H,W) is a pure reinterpretation,
// so proj writes d_out directly row-major [t][c].
//
// Scratch aliasing: the attention output (column-major per window) reuses the
// window-flat input buffer -- g_buf is fully consumed by the QKV GEMM before
// attn_kernel writes it, and all kernels serialize on one stream.
// ---------------------------------------------------------------------------

#define BATCH   16
#define CDIM    768
#define HS      56
#define NHEADS  24
#define HD      32
#define NTOK    49
#define NWIN    64
#define BWIN    (BATCH * NWIN)      // 1024
#define WFLAT   (NTOK * CDIM)       // 37632
#define QSCALE  0.17677669529663687f // 32^-0.5

// Scratch (static device globals; allocation inside kernel_launch is banned)
__device__ float g_buf[BWIN * WFLAT];   // window-flat hwc input; later attn out (aliased)
__device__ float g_q  [BWIN * WFLAT];   // [b_][h][n][d], pre-scaled
__device__ float g_k  [BWIN * WFLAT];   // [b_][h][n][d]
__device__ float g_v  [BWIN * WFLAT];   // [b_][h][n][d]

// ---------------------------------------------------------------------------
// Kernel 1: x (B,C,H,W) -> g_buf[(b*64+win)*37632 + (i*7+j)*768 + c]
// 32x32 smem transpose tiles: read coalesced over w, write coalesced over c.
// grid (B*H = 896, C/32 = 24), block (32, 8)
// ---------------------------------------------------------------------------
__global__ void __launch_bounds__(256) gather_kernel(const float* __restrict__ x)
{
    int bh = blockIdx.x;
    int b  = bh / HS;
    int h  = bh % HS;
    int c0 = blockIdx.y * 32;
    int tx = threadIdx.x, ty = threadIdx.y;

    __shared__ float tile[32][33];

    int wr = h / 7, ii = h % 7;

    for (int w0 = 0; w0 < HS; w0 += 32) {
        int wlim = min(32, HS - w0);
        __syncthreads();
        if (tx < wlim) {
            #pragma unroll
            for (int cy = ty; cy < 32; cy += 8) {
                tile[cy][tx] = x[((b * CDIM + c0 + cy) * HS + h) * HS + w0 + tx];
            }
        }
        __syncthreads();
        for (int wy = ty; wy < wlim; wy += 8) {
            int w   = w0 + wy;
            int win = wr * 8 + (w / 7);
            int n   = ii * 7 + (w % 7);
            g_buf[(b * NWIN + win) * WFLAT + n * CDIM + c0 + tx] = tile[tx][wy];
        }
    }
}

// ---------------------------------------------------------------------------
// GEMM: C[49 x 128] per block. A = per-window column-major flat buffer
// (contiguous tile loads), B = weight (rows = out-channel, K-contiguous).
// BK=32, threads (32,7)=224, per-thread 7x4 register tile.
// MODE 0: A = g_buf, QKV epilogue -> g_q/g_k/g_v ([b_][h][n][d]), q scaled.
// MODE 1: A = g_buf (holding attn out), proj epilogue -> d_out row-major.
// grid (1024, Nout/128)
// ---------------------------------------------------------------------------
template <int MODE>
__global__ void __launch_bounds__(224) gemm49_kernel(const float* __restrict__ W,
                                                     const float* __restrict__ bias,
                                                     float* __restrict__ out)
{
    int b_ = blockIdx.x;
    int n0 = blockIdx.y * 128;
    int tx = threadIdx.x, ty = threadIdx.y;
    int tid = ty * 32 + tx;

    __shared__ float As[32 * 49];    // [k][m], same linear layout as source
    __shared__ float Bs[32 * 132];   // [k][n], pad 132 (16B-aligned rows)

    const float* Ab = g_buf + b_ * WFLAT;

    float acc[7][4];
    #pragma unroll
    for (int i = 0; i < 7; i++)
        #pragma unroll
        for (int j = 0; j < 4; j++) acc[i][j] = 0.0f;

    for (int k0 = 0; k0 < CDIM; k0 += 32) {
        // A tile: 32*49 = 1568 floats, CONTIGUOUS in source
        {
            const float4* asrc = (const float4*)(Ab + k0 * 49);
            float4* adst = (float4*)As;
            for (int i = tid; i < 392; i += 224) adst[i] = asrc[i];
        }
        // B tile: rows n0..n0+127, cols k0..k0+31, store transposed
        for (int i = tid; i < 1024; i += 224) {
            int n  = i >> 3;
            int kq = (i & 7) << 2;
            float4 wv = *(const float4*)(W + (size_t)(n0 + n) * CDIM + k0 + kq);
            Bs[(kq + 0) * 132 + n] = wv.x;
            Bs[(kq + 1) * 132 + n] = wv.y;
            Bs[(kq + 2) * 132 + n] = wv.z;
            Bs[(kq + 3) * 132 + n] = wv.w;
        }
        __syncthreads();

        #pragma unroll
        for (int k = 0; k < 32; k++) {
            float4 bv = *(const float4*)&Bs[k * 132 + tx * 4];
            #pragma unroll
            for (int i = 0; i < 7; i++) {
                float a = As[k * 49 + ty * 7 + i];   // broadcast within warp
                acc[i][0] += a * bv.x;
                acc[i][1] += a * bv.y;
                acc[i][2] += a * bv.z;
                acc[i][3] += a * bv.w;
            }
        }
        __syncthreads();
    }

    int ng = n0 + tx * 4;
    float4 bb = *(const float4*)&bias[ng];

    if (MODE == 0) {
        int which = ng / CDIM;           // constant per block (128 | 768)
        int rem   = ng - which * CDIM;
        int hh = rem >> 5, d0 = rem & 31;
        float* dst = (which == 0) ? g_q : (which == 1 ? g_k : g_v);
        float sc = (which == 0) ? QSCALE : 1.0f;
        #pragma unroll
        for (int i = 0; i < 7; i++) {
            int m = ty * 7 + i;          // token within window, < 49
            float4 o;
            o.x = (acc[i][0] + bb.x) * sc;
            o.y = (acc[i][1] + bb.y) * sc;
            o.z = (acc[i][2] + bb.z) * sc;
            o.w = (acc[i][3] + bb.w) * sc;
            *(float4*)&dst[((b_ * NHEADS + hh) * NTOK + m) * HD + d0] = o;
        }
    } else {
        #pragma unroll
        for (int i = 0; i < 7; i++) {
            int m = ty * 7 + i;
            float4 o;
            o.x = acc[i][0] + bb.x;
            o.y = acc[i][1] + bb.y;
            o.z = acc[i][2] + bb.z;
            o.w = acc[i][3] + bb.w;
            *(float4*)&out[(size_t)(b_ * NTOK + m) * CDIM + ng] = o;
        }
    }
}

// ---------------------------------------------------------------------------
// Kernel 3: fused attention per (window b_, head h). grid (1024, 24), 192 thr.
// S = q k^T (q pre-scaled) + rel-pos bias + mask, softmax, O^T = V^T P^T.
// Writes g_buf[b_*37632 + (h*32+d)*49 + n] (column-major per window for proj;
// aliases the consumed input buffer).
// ---------------------------------------------------------------------------
__global__ void __launch_bounds__(192) attn_kernel(const float* __restrict__ mask,
                                                   const float* __restrict__ bias_table,
                                                   const int*   __restrict__ rel_index)
{
    int b_ = blockIdx.x;
    int h  = blockIdx.y;
    int tid = threadIdx.x;

    __shared__ float qT[32 * 52];    // [d][n]
    __shared__ float kT[32 * 52];    // [d][n]
    __shared__ float Vs[49 * 32];    // [m][d]
    __shared__ float S [52 * 53];    // [n][m], stride 53 (conflict-free)
    __shared__ float rinv[52];

    // ---- load q, k (transposed) and v (natural) ----
    int base = ((b_ * NHEADS + h) * NTOK) * HD;   // fits in int
    {
        const float4* qsrc = (const float4*)(g_q + base);
        const float4* ksrc = (const float4*)(g_k + base);
        const float4* vsrc = (const float4*)(g_v + base);
        for (int i = tid; i < 392; i += 192) {
            int n  = i >> 3;
            int d0 = (i & 7) << 2;
            float4 qv = qsrc[i];
            float4 kv = ksrc[i];
            qT[(d0 + 0) * 52 + n] = qv.x;
            qT[(d0 + 1) * 52 + n] = qv.y;
            qT[(d0 + 2) * 52 + n] = qv.z;
            qT[(d0 + 3) * 52 + n] = qv.w;
            kT[(d0 + 0) * 52 + n] = kv.x;
            kT[(d0 + 1) * 52 + n] = kv.y;
            kT[(d0 + 2) * 52 + n] = kv.z;
            kT[(d0 + 3) * 52 + n] = kv.w;
            ((float4*)Vs)[i] = vsrc[i];
        }
    }
    __syncthreads();

    // ---- S = q k^T : 13x13 thread grid, 4x4 register tile ----
    if (tid < 169) {
        int tx = tid % 13, ty = tid / 13;
        float acc[4][4];
        #pragma unroll
        for (int i = 0; i < 4; i++)
            #pragma unroll
            for (int j = 0; j < 4; j++) acc[i][j] = 0.0f;

        #pragma unroll
        for (int d = 0; d < 32; d++) {
            float4 av = *(const float4*)&qT[d * 52 + ty * 4];
            float4 bv = *(const float4*)&kT[d * 52 + tx * 4];
            acc[0][0] += av.x * bv.x; acc[0][1] += av.x * bv.y; acc[0][2] += av.x * bv.z; acc[0][3] += av.x * bv.w;
            acc[1][0] += av.y * bv.x; acc[1][1] += av.y * bv.y; acc[1][2] += av.y * bv.z; acc[1][3] += av.y * bv.w;
            acc[2][0] += av.z * bv.x; acc[2][1] += av.z * bv.y; acc[2][2] += av.z * bv.z; acc[2][3] += av.z * bv.w;
            acc[3][0] += av.w * bv.x; acc[3][1] += av.w * bv.y; acc[3][2] += av.w * bv.z; acc[3][3] += av.w * bv.w;
        }
        #pragma unroll
        for (int i = 0; i < 4; i++) {
            int r = ty * 4 + i;
            if (r < NTOK) {
                #pragma unroll
                for (int j = 0; j < 4; j++) S[r * 53 + tx * 4 + j] = acc[i][j];
            }
        }
    }
    __syncthreads();

    // ---- softmax rows (bias + mask folded in; 1/sum deferred to PV) ----
    if (tid < NTOK) {
        int r = tid;
        int win = b_ & (NWIN - 1);
        const float* mrow = mask + ((size_t)win * NTOK + r) * NTOK;
        const int*   rrow = rel_index + r * NTOK;
        float mx = -1e30f;
        for (int m = 0; m < NTOK; m++) {
            float s = S[r * 53 + m] + bias_table[rrow[m] * NHEADS + h] + mrow[m];
            S[r * 53 + m] = s;
            mx = fmaxf(mx, s);
        }
        float sum = 0.0f;
        for (int m = 0; m < NTOK; m++) {
            float e = __expf(S[r * 53 + m] - mx);
            S[r * 53 + m] = e;
            sum += e;
        }
        rinv[r] = 1.0f / sum;
    }
    __syncthreads();

    // ---- O^T[d][n] = sum_m V[m][d] * P[n][m] : 13(n) x 8(d) threads ----
    if (tid < 104) {
        int tx = tid % 13;   // n-group
        int ty = tid / 13;   // d-group
        float acc[4][4];     // [d][n]
        #pragma unroll
        for (int i = 0; i < 4; i++)
            #pragma unroll
            for (int j = 0; j < 4; j++) acc[i][j] = 0.0f;

        for (int m = 0; m < NTOK; m++) {
            float4 av = *(const float4*)&Vs[m * 32 + ty * 4];
            #pragma unroll
            for (int j = 0; j < 4; j++) {
                int n = tx * 4 + j;
                float p = (n < NTOK) ? S[n * 53 + m] : 0.0f;
                acc[0][j] += av.x * p;
                acc[1][j] += av.y * p;
                acc[2][j] += av.z * p;
                acc[3][j] += av.w * p;
            }
        }
        float* ob = g_buf + b_ * WFLAT + (h * HD) * NTOK;
        #pragma unroll
        for (int j = 0; j < 4; j++) {
            int n = tx * 4 + j;
            if (n < NTOK) {
                float iv = rinv[n];
                #pragma unroll
                for (int i = 0; i < 4; i++)
                    ob[(ty * 4 + i) * NTOK + n] = acc[i][j] * iv;
            }
        }
    }
}

// ---------------------------------------------------------------------------
extern "C" void kernel_launch(void* const* d_in, const int* in_sizes, int n_in,
                              void* d_out, int out_size)
{
    const float* x          = (const float*)d_in[0];
    const float* mask       = (const float*)d_in[1];
    const float* qkv_w      = (const float*)d_in[2];
    const float* qkv_b      = (const float*)d_in[3];
    const float* proj_w     = (const float*)d_in[4];
    const float* proj_b     = (const float*)d_in[5];
    const float* bias_table = (const float*)d_in[6];
    const int*   rel_index  = (const int*)d_in[7];
    float* out = (float*)d_out;

    gather_kernel<<<dim3(BATCH * HS, CDIM / 32), dim3(32, 8)>>>(x);
    gemm49_kernel<0><<<dim3(BWIN, (3 * CDIM) / 128), dim3(32, 7)>>>(qkv_w, qkv_b, nullptr);
    attn_kernel<<<dim3(BWIN, NHEADS), 192>>>(mask, bias_table, rel_index);
    gemm49_kernel<1><<<dim3(BWIN, CDIM / 128), dim3(32, 7)>>>(proj_w, proj_b, out);
}

// round 5
// speedup vs baseline: 2.4525x; 2.4525x over previous
#include <cuda_runtime.h>
#include <cuda_bf16.h>
#include <cstdint>

// ---------------------------------------------------------------------------
// WindowAttention (Swin-style, faithful to the reference's raw-view scramble).
// GEMMs on tensor cores (tf32 mma.sync, fp32 accumulate); attention in fp32.
//
// Shapes: B=16, C=768, H=W=56, window 7x7 (N=49), heads=24, hd=32,
// B_ = 1024 windows, T = 50176 tokens.
//
// Layout identity: xt[n][c] = window_hwc.flat[c*49+n]  (per window), so the
// per-window GEMM A-matrix is the (49x768) hwc matrix stored column-major ->
// contiguous [k][m] tiles. The final (B_,N,C)->(B,C,H,W) reshape is a pure
// reinterpretation -> proj writes d_out directly row-major.
// ---------------------------------------------------------------------------

#define BATCH   16
#define CDIM    768
#define HS      56
#define NHEADS  24
#define HD      32
#define NTOK    49
#define NWIN    64
#define BWIN    (BATCH * NWIN)      // 1024
#define WFLAT   (NTOK * CDIM)       // 37632
#define QSCALE  0.17677669529663687f

// Scratch (static device globals; allocation is banned)
__device__ float g_buf[BWIN * WFLAT];   // window-flat hwc input; later attn out (aliased)
__device__ float g_q  [BWIN * WFLAT];   // [b_][h][n][d], pre-scaled
__device__ float g_k  [BWIN * WFLAT];
__device__ float g_v  [BWIN * WFLAT];

// ---------------------------------------------------------------------------
__device__ __forceinline__ uint32_t f2tf(float f) {
    uint32_t u;
    asm("cvt.rna.tf32.f32 %0, %1;" : "=r"(u) : "f"(f));
    return u;
}

__device__ __forceinline__ void mma_tf32(float* c, const uint32_t* a, const uint32_t* b) {
    asm volatile(
        "mma.sync.aligned.m16n8k8.row.col.f32.tf32.tf32.f32 "
        "{%0,%1,%2,%3},{%4,%5,%6,%7},{%8,%9},{%0,%1,%2,%3};"
        : "+f"(c[0]), "+f"(c[1]), "+f"(c[2]), "+f"(c[3])
        : "r"(a[0]), "r"(a[1]), "r"(a[2]), "r"(a[3]), "r"(b[0]), "r"(b[1]));
}

// ---------------------------------------------------------------------------
// Kernel 1: x (B,C,H,W) -> g_buf[(b*64+win)*37632 + (i*7+j)*768 + c]
// ---------------------------------------------------------------------------
__global__ void __launch_bounds__(256) gather_kernel(const float* __restrict__ x)
{
    int bh = blockIdx.x;
    int b  = bh / HS;
    int h  = bh % HS;
    int c0 = blockIdx.y * 32;
    int tx = threadIdx.x, ty = threadIdx.y;

    __shared__ float tile[32][33];

    int wr = h / 7, ii = h % 7;

    for (int w0 = 0; w0 < HS; w0 += 32) {
        int wlim = min(32, HS - w0);
        __syncthreads();
        if (tx < wlim) {
            #pragma unroll
            for (int cy = ty; cy < 32; cy += 8)
                tile[cy][tx] = x[((b * CDIM + c0 + cy) * HS + h) * HS + w0 + tx];
        }
        __syncthreads();
        for (int wy = ty; wy < wlim; wy += 8) {
            int w   = w0 + wy;
            int win = wr * 8 + (w / 7);
            int n   = ii * 7 + (w % 7);
            g_buf[(b * NWIN + win) * WFLAT + n * CDIM + c0 + tx] = tile[tx][wy];
        }
    }
}

// ---------------------------------------------------------------------------
// Tensor-core GEMM. Block: BM=128 rows (2 windows x 64-pad) x BN=128 cols,
// K=768 in BK=32 chunks. 256 threads = 8 warps, warp grid 2(m) x 4(n),
// each warp 4x4 m16n8k8 tiles. smem tiles stored K-innermost, ld=36
// (conflict-free fragment loads: bank = lane + const).
// MODE 0: A=g_buf, epilogue -> g_q/g_k/g_v. MODE 1: A=g_buf, -> d_out.
// grid (512, Nout/128)
// ---------------------------------------------------------------------------
#define LDT 36

template <int MODE>
__global__ void __launch_bounds__(256) gemm_tc_kernel(const float* __restrict__ W,
                                                      const float* __restrict__ bias,
                                                      float* __restrict__ out)
{
    int n0  = blockIdx.y * 128;
    int tid = threadIdx.x;
    int lane = tid & 31, warp = tid >> 5;
    int grp = lane >> 2, tig = lane & 3;
    int warp_m = warp & 1;          // 2
    int warp_n = warp >> 1;         // 4

    __shared__ uint32_t As[128 * LDT];   // [m][k], k in 0..31
    __shared__ uint32_t Bs[128 * LDT];   // [n][k]

    const float* A0 = g_buf + (size_t)(2 * blockIdx.x)     * WFLAT;
    const float* A1 = g_buf + (size_t)(2 * blockIdx.x + 1) * WFLAT;

    float acc[4][4][4];
    #pragma unroll
    for (int i = 0; i < 4; i++)
        #pragma unroll
        for (int j = 0; j < 4; j++)
            #pragma unroll
            for (int r = 0; r < 4; r++) acc[i][j][r] = 0.0f;

    for (int k0 = 0; k0 < CDIM; k0 += 32) {
        // ---- A tiles: two contiguous 49x32 chunks ([k][m] in source) ----
        const float* s0 = A0 + k0 * NTOK;
        const float* s1 = A1 + k0 * NTOK;
        #pragma unroll
        for (int it = 0; it < 7; it++) {
            int i = tid + it * 256;
            if (i < 1568) {
                int k = i / 49, m = i - k * 49;
                As[m * LDT + k]        = f2tf(s0[i]);
                As[(64 + m) * LDT + k] = f2tf(s1[i]);
            }
        }
        // ---- B tile: W rows n0..n0+127, cols k0..k0+31 ----
        #pragma unroll
        for (int it = 0; it < 4; it++) {
            int i  = tid + it * 256;
            int n  = i >> 3;
            int kq = (i & 7) << 2;
            float4 wv = *(const float4*)(W + (size_t)(n0 + n) * CDIM + k0 + kq);
            uint32_t* d = &Bs[n * LDT + kq];
            d[0] = f2tf(wv.x); d[1] = f2tf(wv.y); d[2] = f2tf(wv.z); d[3] = f2tf(wv.w);
        }
        __syncthreads();

        #pragma unroll
        for (int ks = 0; ks < 4; ks++) {
            int k8 = ks * 8;
            uint32_t afr[4][4], bfr[4][2];
            #pragma unroll
            for (int mt = 0; mt < 4; mt++) {
                int m = warp_m * 64 + mt * 16 + grp;
                afr[mt][0] = As[m * LDT + k8 + tig];
                afr[mt][1] = As[(m + 8) * LDT + k8 + tig];
                afr[mt][2] = As[m * LDT + k8 + tig + 4];
                afr[mt][3] = As[(m + 8) * LDT + k8 + tig + 4];
            }
            #pragma unroll
            for (int nt = 0; nt < 4; nt++) {
                int n = warp_n * 32 + nt * 8 + grp;
                bfr[nt][0] = Bs[n * LDT + k8 + tig];
                bfr[nt][1] = Bs[n * LDT + k8 + tig + 4];
            }
            #pragma unroll
            for (int mt = 0; mt < 4; mt++)
                #pragma unroll
                for (int nt = 0; nt < 4; nt++)
                    mma_tf32(acc[mt][nt], afr[mt], bfr[nt]);
        }
        __syncthreads();
    }

    // ---- epilogue ----
    #pragma unroll
    for (int nt = 0; nt < 4; nt++) {
        int n_loc = warp_n * 32 + nt * 8 + 2 * tig;
        int n_g   = n0 + n_loc;
        float2 bb = *(const float2*)&bias[n_g];

        int which = 0, h = 0, d = 0;
        float sc = 1.0f;
        float* dst0 = nullptr;
        if (MODE == 0) {
            which = n_g / CDIM;                 // constant per block
            int rem = n_g - which * CDIM;
            h = rem >> 5; d = rem & 31;
            dst0 = (which == 0) ? g_q : (which == 1 ? g_k : g_v);
            sc = (which == 0) ? QSCALE : 1.0f;
        }

        #pragma unroll
        for (int mt = 0; mt < 4; mt++) {
            #pragma unroll
            for (int half = 0; half < 2; half++) {
                int m   = warp_m * 64 + mt * 16 + grp + half * 8;
                int win = m >> 6;
                int tok = m & 63;
                if (tok < NTOK) {
                    int b_ = 2 * blockIdx.x + win;
                    float c0 = acc[mt][nt][half * 2 + 0];
                    float c1 = acc[mt][nt][half * 2 + 1];
                    if (MODE == 0) {
                        float2 o = make_float2((c0 + bb.x) * sc, (c1 + bb.y) * sc);
                        *(float2*)&dst0[((b_ * NHEADS + h) * NTOK + tok) * HD + d] = o;
                    } else {
                        float2 o = make_float2(c0 + bb.x, c1 + bb.y);
                        *(float2*)&out[(size_t)(b_ * NTOK + tok) * CDIM + n_g] = o;
                    }
                }
            }
        }
    }
}

// ---------------------------------------------------------------------------
// Fused attention per (window b_, head h). grid (1024, 24), 192 thr. fp32.
// Writes g_buf[b_*37632 + (h*32+d)*49 + n] (column-major per window).
// ---------------------------------------------------------------------------
__global__ void __launch_bounds__(192) attn_kernel(const float* __restrict__ mask,
                                                   const float* __restrict__ bias_table,
                                                   const int*   __restrict__ rel_index)
{
    int b_ = blockIdx.x;
    int h  = blockIdx.y;
    int tid = threadIdx.x;

    __shared__ float qT[32 * 52];    // [d][n]
    __shared__ float kT[32 * 52];    // [d][n]
    __shared__ float Vs[49 * 32];    // [m][d]
    __shared__ float S [52 * 53];    // [n][m]
    __shared__ float rinv[52];

    int base = ((b_ * NHEADS + h) * NTOK) * HD;
    {
        const float4* qsrc = (const float4*)(g_q + base);
        const float4* ksrc = (const float4*)(g_k + base);
        const float4* vsrc = (const float4*)(g_v + base);
        for (int i = tid; i < 392; i += 192) {
            int n  = i >> 3;
            int d0 = (i & 7) << 2;
            float4 qv = qsrc[i];
            float4 kv = ksrc[i];
            qT[(d0 + 0) * 52 + n] = qv.x;
            qT[(d0 + 1) * 52 + n] = qv.y;
            qT[(d0 + 2) * 52 + n] = qv.z;
            qT[(d0 + 3) * 52 + n] = qv.w;
            kT[(d0 + 0) * 52 + n] = kv.x;
            kT[(d0 + 1) * 52 + n] = kv.y;
            kT[(d0 + 2) * 52 + n] = kv.z;
            kT[(d0 + 3) * 52 + n] = kv.w;
            ((float4*)Vs)[i] = vsrc[i];
        }
    }
    __syncthreads();

    if (tid < 169) {
        int tx = tid % 13, ty = tid / 13;
        float acc[4][4];
        #pragma unroll
        for (int i = 0; i < 4; i++)
            #pragma unroll
            for (int j = 0; j < 4; j++) acc[i][j] = 0.0f;

        #pragma unroll
        for (int d = 0; d < 32; d++) {
            float4 av = *(const float4*)&qT[d * 52 + ty * 4];
            float4 bv = *(const float4*)&kT[d * 52 + tx * 4];
            acc[0][0] += av.x * bv.x; acc[0][1] += av.x * bv.y; acc[0][2] += av.x * bv.z; acc[0][3] += av.x * bv.w;
            acc[1][0] += av.y * bv.x; acc[1][1] += av.y * bv.y; acc[1][2] += av.y * bv.z; acc[1][3] += av.y * bv.w;
            acc[2][0] += av.z * bv.x; acc[2][1] += av.z * bv.y; acc[2][2] += av.z * bv.z; acc[2][3] += av.z * bv.w;
            acc[3][0] += av.w * bv.x; acc[3][1] += av.w * bv.y; acc[3][2] += av.w * bv.z; acc[3][3] += av.w * bv.w;
        }
        #pragma unroll
        for (int i = 0; i < 4; i++) {
            int r = ty * 4 + i;
            if (r < NTOK) {
                #pragma unroll
                for (int j = 0; j < 4; j++) S[r * 53 + tx * 4 + j] = acc[i][j];
            }
        }
    }
    __syncthreads();

    if (tid < NTOK) {
        int r = tid;
        int win = b_ & (NWIN - 1);
        const float* mrow = mask + ((size_t)win * NTOK + r) * NTOK;
        const int*   rrow = rel_index + r * NTOK;
        float mx = -1e30f;
        for (int m = 0; m < NTOK; m++) {
            float s = S[r * 53 + m] + bias_table[rrow[m] * NHEADS + h] + mrow[m];
            S[r * 53 + m] = s;
            mx = fmaxf(mx, s);
        }
        float sum = 0.0f;
        for (int m = 0; m < NTOK; m++) {
            float e = __expf(S[r * 53 + m] - mx);
            S[r * 53 + m] = e;
            sum += e;
        }
        rinv[r] = 1.0f / sum;
    }
    __syncthreads();

    if (tid < 104) {
        int tx = tid % 13;   // n-group
        int ty = tid / 13;   // d-group
        float acc[4][4];
        #pragma unroll
        for (int i = 0; i < 4; i++)
            #pragma unroll
            for (int j = 0; j < 4; j++) acc[i][j] = 0.0f;

        for (int m = 0; m < NTOK; m++) {
            float4 av = *(const float4*)&Vs[m * 32 + ty * 4];
            #pragma unroll
            for (int j = 0; j < 4; j++) {
                int n = tx * 4 + j;
                float p = (n < NTOK) ? S[n * 53 + m] : 0.0f;
                acc[0][j] += av.x * p;
                acc[1][j] += av.y * p;
                acc[2][j] += av.z * p;
                acc[3][j] += av.w * p;
            }
        }
        float* ob = g_buf + (size_t)b_ * WFLAT + (h * HD) * NTOK;
        #pragma unroll
        for (int j = 0; j < 4; j++) {
            int n = tx * 4 + j;
            if (n < NTOK) {
                float iv = rinv[n];
                #pragma unroll
                for (int i = 0; i < 4; i++)
                    ob[(ty * 4 + i) * NTOK + n] = acc[i][j] * iv;
            }
        }
    }
}

// ---------------------------------------------------------------------------
extern "C" void kernel_launch(void* const* d_in, const int* in_sizes, int n_in,
                              void* d_out, int out_size)
{
    const float* x          = (const float*)d_in[0];
    const float* mask       = (const float*)d_in[1];
    const float* qkv_w      = (const float*)d_in[2];
    const float* qkv_b      = (const float*)d_in[3];
    const float* proj_w     = (const float*)d_in[4];
    const float* proj_b     = (const float*)d_in[5];
    const float* bias_table = (const float*)d_in[6];
    const int*   rel_index  = (const int*)d_in[7];
    float* out = (float*)d_out;

    gather_kernel<<<dim3(BATCH * HS, CDIM / 32), dim3(32, 8)>>>(x);
    gemm_tc_kernel<0><<<dim3(BWIN / 2, (3 * CDIM) / 128), 256>>>(qkv_w, qkv_b, nullptr);
    attn_kernel<<<dim3(BWIN, NHEADS), 192>>>(mask, bias_table, rel_index);
    gemm_tc_kernel<1><<<dim3(BWIN / 2, CDIM / 128), 256>>>(proj_w, proj_b, out);
}